// round 13
// baseline (speedup 1.0000x reference)
#include <cuda_runtime.h>
#include <cuda_bf16.h>

typedef unsigned int u32;
typedef unsigned long long u64;

#define NTHREADS 512
#define RTILE 128
#define SA 296              // A-buffer row stride (bf16 elems); 592B = conflict-free

// ---------------- smem map (bytes) ----------------------------------------------
#define SST_OFF  0          // state tile: 128*50*4 = 25600
#define A0_OFF   25600      // A buffer 0: 128*296*2 = 75776
#define A1_OFF   101376     // A buffer 1: 75776
#define WB_OFF   177152     // weight chunk ring: 2 x 18944 = 37888
#define SMEM_TOTAL 215040

// ---------------- weight image offsets (bf16 elems) ------------------------------
// image: [n rows][SB cols]: [0,K)=hi(W[k][n]), [K,2K)=lo, rest pad
#define G_H2 0       // 64 x 136
#define G_H3 8704
#define G_B2 17408   // 80 x 168
#define G_B3 30848
#define G_C1 44288   // 144 x 296
#define G_C2 86912   // 64 x 296
#define G_C3 105856  // 64 x 136
#define G_TOTAL 114560

__device__ float g_TH[4 * 19 * 64];
__device__ float g_TB[5 * 19 * 80];
__device__ __align__(16) __nv_bfloat16 g_WB[G_TOTAL];

// ---------------- output segment descriptors -------------------------------------
__device__ const int c_kind[39] = {0,0,0,0,0,0,0,0,
                                   1,1, 1,1,1,1,1, 1,1,1,1,1,
                                   2,2,2,2, 1,1,1, 2, 1,1,1, 1, 1,
                                   2,2,2,2,2,2};
__device__ const int c_p0[39]   = {0,0,0,0,0,0,0,0,
                                   3,0, 2,2,2,2,2, 0,0,0,0,0,
                                   40,41,42,43, 0,1,5, 39, 1,0,5, 4, 0,
                                   44,45,46,47,48,49};
__device__ const int c_p1[39]   = {0,0,0,0,0,0,0,0,
                                   18,20, 22,23,24,25,26, 27,28,29,30,31,
                                   0,2,3,5, 35,36,37, 1, 32,33,34, 19, 38,
                                   4,4,4,4,4,4};

__device__ __forceinline__ float leaky(float x) { return x > 0.f ? x : 0.01f * x; }

__device__ __forceinline__ u32 smem_u32(const void* p) {
    u32 a;
    asm("{ .reg .u64 t; cvta.to.shared.u64 t, %1; cvt.u32.u64 %0, t; }" : "=r"(a) : "l"(p));
    return a;
}
__device__ __forceinline__ void ldsm_x4(u32* r, u32 addr) {
    asm volatile("ldmatrix.sync.aligned.m8n8.x4.shared.b16 {%0,%1,%2,%3}, [%4];"
                 : "=r"(r[0]), "=r"(r[1]), "=r"(r[2]), "=r"(r[3]) : "r"(addr));
}
__device__ __forceinline__ void mma16816(float* d, const u32* a, const u32* b) {
    asm volatile("mma.sync.aligned.m16n8k16.row.col.f32.bf16.bf16.f32 "
                 "{%0,%1,%2,%3}, {%4,%5,%6,%7}, {%8,%9}, {%0,%1,%2,%3};"
                 : "+f"(d[0]), "+f"(d[1]), "+f"(d[2]), "+f"(d[3])
                 : "r"(a[0]), "r"(a[1]), "r"(a[2]), "r"(a[3]), "r"(b[0]), "r"(b[1]));
}
__device__ __forceinline__ void cp16(u32 dst, const void* src) {
    asm volatile("cp.async.cg.shared.global [%0], [%1], 16;" :: "r"(dst), "l"(src));
}

__device__ __forceinline__ u32 bf16pack(float v0, float v1, float& l0, float& l1) {
    __nv_bfloat16 h0 = __float2bfloat16(v0), h1 = __float2bfloat16(v1);
    l0 = v0 - __bfloat162float(h0); l1 = v1 - __bfloat162float(h1);
    return (u32)__bfloat16_as_ushort(h0) | ((u32)__bfloat16_as_ushort(h1) << 16);
}
__device__ __forceinline__ u32 bf16pack2(float v0, float v1) {
    return (u32)__bfloat16_as_ushort(__float2bfloat16(v0)) |
           ((u32)__bfloat16_as_ushort(__float2bfloat16(v1)) << 16);
}

// ---------------- prologue 1: embedding->layer1 fp32 tables ----------------------
__global__ void build_tables_kernel(const float* __restrict__ suit_emb,
                                    const float* __restrict__ rank_emb,
                                    const float* __restrict__ hW1,
                                    const float* __restrict__ bW1)
{
    int i = blockIdx.x * blockDim.x + threadIdx.x;
    if (i < 4 * 19 * 64) {
        int j = i & 63, e = (i >> 6) % 19, c = i / (64 * 19);
        const float* emb; int dbase;
        if (e < 5) { emb = suit_emb + e * 8;        dbase = 16 * c; }
        else       { emb = rank_emb + (e - 5) * 8;  dbase = 16 * c + 8; }
        float s = 0.f;
        #pragma unroll
        for (int d = 0; d < 8; d++) s += emb[d] * hW1[(dbase + d) * 64 + j];
        g_TH[i] = s;
    } else {
        int ib = i - 4 * 19 * 64;
        if (ib < 5 * 19 * 80) {
            int j = ib % 80, e = (ib / 80) % 19, c = ib / (80 * 19);
            const float* emb; int dbase;
            if (e < 5) { emb = suit_emb + e * 8;       dbase = 16 * c; }
            else       { emb = rank_emb + (e - 5) * 8; dbase = 16 * c + 8; }
            float s = 0.f;
            #pragma unroll
            for (int d = 0; d < 8; d++) s += emb[d] * bW1[(dbase + d) * 80 + j];
            g_TB[ib] = s;
        }
    }
}

// ---------------- prologue 2: split weights into bf16 hi/lo images ---------------
__device__ __forceinline__ void pack_img(const float* __restrict__ W,
                                         int N, int K, int SB, int base, int e)
{
    int n = e / SB, c = e - n * SB;
    __nv_bfloat16 v;
    if (c < K) {
        v = __float2bfloat16(W[c * N + n]);
    } else if (c < 2 * K) {
        float w = W[(c - K) * N + n];
        __nv_bfloat16 h = __float2bfloat16(w);
        v = __float2bfloat16(w - __bfloat162float(h));
    } else {
        v = __float2bfloat16(0.f);
    }
    g_WB[base + e] = v;
}

__global__ void pack_wb_kernel(const float* __restrict__ hW2, const float* __restrict__ hW3,
                               const float* __restrict__ bW2, const float* __restrict__ bW3,
                               const float* __restrict__ cW1, const float* __restrict__ cW2,
                               const float* __restrict__ cW3)
{
    int i = blockIdx.x * blockDim.x + threadIdx.x;
    if      (i < G_H3)    pack_img(hW2, 64,  64,  136, G_H2, i - G_H2);
    else if (i < G_B2)    pack_img(hW3, 64,  64,  136, G_H3, i - G_H3);
    else if (i < G_B3)    pack_img(bW2, 80,  80,  168, G_B2, i - G_B2);
    else if (i < G_C1)    pack_img(bW3, 80,  80,  168, G_B3, i - G_B3);
    else if (i < G_C2)    pack_img(cW1, 144, 144, 296, G_C1, i - G_C1);
    else if (i < G_C3)    pack_img(cW2, 64,  144, 296, G_C2, i - G_C2);
    else if (i < G_TOTAL) pack_img(cW3, 64,  64,  136, G_C3, i - G_C3);
}

// ---------------- mma.sync layer (16 warps, cp.async weight pipeline) ------------
// A row-major [128][SA] bf16: hi cols [hiIn,hiIn+K), lo [loIn,loIn+K).
// Warp (rw=wid&7, wg=wid>>3): rows 16rw..16rw+15, 8-col tiles t==wg (mod 2).
// Weights stream in 32-row chunks via cp.async into a 2-deep smem ring.
// Each (tile, pass) has its OWN fp32 accumulator -> 6 independent HMMA streams.
template<int K, int SB, bool ACT, bool FINAL>
__device__ void layer_mma(char* smemc, u32 su, int ainOff, int aoutOff,
                          int hiIn, int loIn, int hiOut, int loOut, int NTOT,
                          const __nv_bfloat16* gimg, const float* __restrict__ bias,
                          int wid, int lane, int tid)
{
    const int rw = wid & 7, wg = wid >> 3;
    const int m0 = rw * 16;
    const u32 aBase = su + (u32)ainOff + ((u32)(m0 + (lane & 15)) * SA + ((lane >> 4) << 3)) * 2;

    constexpr int CHUNKB = 32 * SB * 2;     // bytes per ring slot
    const int nch = (NTOT + 31) / 32;

    auto issue = [&](int c) {
        const int n0 = c * 32;
        const int cn = (NTOT - n0) < 32 ? (NTOT - n0) : 32;
        const int bytes = cn * SB * 2;
        const char* src = (const char*)gimg + (size_t)n0 * SB * 2;
        const u32 dst = su + WB_OFF + (u32)(c & 1) * CHUNKB;
        for (int i = tid * 16; i < bytes; i += NTHREADS * 16) cp16(dst + i, src + i);
        asm volatile("cp.async.commit_group;" ::: "memory");
    };
    issue(0);

    for (int c = 0; c < nch; c++) {
        if (c + 1 < nch) {
            issue(c + 1);
            asm volatile("cp.async.wait_group 1;" ::: "memory");
        } else {
            asm volatile("cp.async.wait_group 0;" ::: "memory");
        }
        __syncthreads();

        const int n0 = c * 32;
        const int cn = (NTOT - n0) < 32 ? (NTOT - n0) : 32;
        const int nt = cn >> 3;                       // 8-col tiles in chunk (2 or 4)
        const bool has1 = (wg + 2) < nt;
        const int tsel = (lane < 16) ? wg : (has1 ? wg + 2 : wg);
        const u32 wbase = su + WB_OFF + (u32)(c & 1) * CHUNKB;
        const u32 bLane = wbase + ((u32)(tsel * 8 + (lane & 7)) * SB + (u32)(((lane >> 3) & 1) * 8)) * 2;

        // independent accumulator per (tile, pass): 6 parallel HMMA chains
        float acc[2][3][4];
        #pragma unroll
        for (int t = 0; t < 2; t++)
            #pragma unroll
            for (int p = 0; p < 3; p++)
                #pragma unroll
                for (int q = 0; q < 4; q++) acc[t][p][q] = 0.f;

        #pragma unroll
        for (int ks = 0; ks < K / 16; ks++) {
            const u32 ko = (u32)(ks * 16) * 2;
            u32 ah[4], al[4], bh[4], bl[4];
            ldsm_x4(ah, aBase + (u32)hiIn * 2 + ko);
            ldsm_x4(al, aBase + (u32)loIn * 2 + ko);
            ldsm_x4(bh, bLane + ko);                 // tiles wg (r0,r1) and wg+2 (r2,r3)
            ldsm_x4(bl, bLane + (u32)K * 2 + ko);
            mma16816(acc[0][0], ah, &bh[0]);
            mma16816(acc[0][1], ah, &bl[0]);
            mma16816(acc[0][2], al, &bh[0]);
            if (has1) {
                mma16816(acc[1][0], ah, &bh[2]);
                mma16816(acc[1][1], ah, &bl[2]);
                mma16816(acc[1][2], al, &bh[2]);
            }
        }

        // epilogue: sum passes, bias (+leaky), split-store own rows/cols
        const int g2 = lane >> 2, tt = lane & 3;
        const int r0 = m0 + g2, r1 = r0 + 8;
        #pragma unroll
        for (int ti = 0; ti < 2; ti++) {
            if (ti == 1 && !has1) break;
            const int col = n0 + (wg + 2 * ti) * 8 + 2 * tt;
            float b0 = __ldg(bias + col), b1 = __ldg(bias + col + 1);
            float v00 = (acc[ti][0][0] + acc[ti][1][0]) + acc[ti][2][0] + b0;
            float v01 = (acc[ti][0][1] + acc[ti][1][1]) + acc[ti][2][1] + b1;
            float v10 = (acc[ti][0][2] + acc[ti][1][2]) + acc[ti][2][2] + b0;
            float v11 = (acc[ti][0][3] + acc[ti][1][3]) + acc[ti][2][3] + b1;
            if (ACT) { v00 = leaky(v00); v01 = leaky(v01); v10 = leaky(v10); v11 = leaky(v11); }
            if (FINAL) {
                float* f = (float*)(smemc + aoutOff);
                *(float2*)(f + r0 * 64 + col) = make_float2(v00, v01);
                *(float2*)(f + r1 * 64 + col) = make_float2(v10, v11);
            } else {
                char* ab = smemc + aoutOff;
                float l00, l01, l10, l11;
                u32 h0 = bf16pack(v00, v01, l00, l01);
                u32 h1 = bf16pack(v10, v11, l10, l11);
                *(u32*)(ab + ((size_t)r0 * SA + hiOut + col) * 2) = h0;
                *(u32*)(ab + ((size_t)r1 * SA + hiOut + col) * 2) = h1;
                *(u32*)(ab + ((size_t)r0 * SA + loOut + col) * 2) = bf16pack2(l00, l01);
                *(u32*)(ab + ((size_t)r1 * SA + loOut + col) * 2) = bf16pack2(l10, l11);
            }
        }
        __syncthreads();    // ring slot reuse + cross-warp A visibility
    }
}

// ---------------- fused main kernel ---------------------------------------------
__global__ void __launch_bounds__(NTHREADS, 1)
preprocess_kernel(const float* __restrict__ state,
                  const float* __restrict__ hand_b1, const float* __restrict__ board_b1,
                  const float* __restrict__ hand_b2, const float* __restrict__ hand_b3,
                  const float* __restrict__ board_b2, const float* __restrict__ board_b3,
                  const float* __restrict__ hb_b1, const float* __restrict__ hb_b2,
                  const float* __restrict__ hb_b3,
                  const float* __restrict__ pos_emb, const float* __restrict__ action_emb,
                  const float* __restrict__ active_emb, const float* __restrict__ street_emb,
                  const float* __restrict__ nump_emb, const float* __restrict__ blind_emb,
                  const float* __restrict__ scalar_W, const float* __restrict__ scalar_b,
                  float* __restrict__ out)
{
    extern __shared__ char smemc[];
    const u32 su = smem_u32(smemc);
    const int tid = threadIdx.x, lane = tid & 31, wid = tid >> 5;
    const int row0 = blockIdx.x * RTILE;
    float* sst = (float*)(smemc + SST_OFF);

    for (int i = tid; i < RTILE * 50; i += NTHREADS) sst[i] = __ldg(state + (size_t)row0 * 50 + i);
    __syncthreads();

    // ---- phase 1: exact fp32 table-sum layer-1, split-store into A0 -------------
    char* a0 = smemc + A0_OFF;
    for (int i = tid; i < RTILE * 32; i += NTHREADS) {
        int row = i >> 5, cp = (i & 31) * 2;
        const float* st = sst + row * 50;
        float s0 = __ldg(hand_b1 + cp), s1 = __ldg(hand_b1 + cp + 1);
        #pragma unroll
        for (int c = 0; c < 4; c++) {
            int r = (int)st[2 * c], sv = (int)st[2 * c + 1];
            float2 t1 = *(const float2*)&g_TH[(c * 19 + sv) * 64 + cp];
            float2 t2 = *(const float2*)&g_TH[(c * 19 + 5 + r) * 64 + cp];
            s0 += t1.x + t2.x; s1 += t1.y + t2.y;
        }
        s0 = leaky(s0); s1 = leaky(s1);
        float l0, l1;
        *(u32*)(a0 + ((size_t)row * SA + cp) * 2)       = bf16pack(s0, s1, l0, l1);
        *(u32*)(a0 + ((size_t)row * SA + 144 + cp) * 2) = bf16pack2(l0, l1);
    }
    for (int i = tid; i < RTILE * 40; i += NTHREADS) {
        int row = i / 40, cp = (i % 40) * 2;
        const float* st = sst + row * 50;
        float s0 = __ldg(board_b1 + cp), s1 = __ldg(board_b1 + cp + 1);
        #pragma unroll
        for (int c = 0; c < 5; c++) {
            int r = (int)st[8 + 2 * c], sv = (int)st[9 + 2 * c];
            float2 t1 = *(const float2*)&g_TB[(c * 19 + sv) * 80 + cp];
            float2 t2 = *(const float2*)&g_TB[(c * 19 + 5 + r) * 80 + cp];
            s0 += t1.x + t2.x; s1 += t1.y + t2.y;
        }
        s0 = leaky(s0); s1 = leaky(s1);
        float l0, l1;
        *(u32*)(a0 + ((size_t)row * SA + 64 + cp) * 2)  = bf16pack(s0, s1, l0, l1);
        *(u32*)(a0 + ((size_t)row * SA + 208 + cp) * 2) = bf16pack2(l0, l1);
    }
    __syncthreads();

    // ---- MLP chain via mma.sync (bf16 3-pass split) ------------------------------
    layer_mma< 64, 136, true , false>(smemc, su, A0_OFF, A1_OFF, 0, 144, 0, 144, 64,
                                      g_WB + G_H2, hand_b2,  wid, lane, tid);
    layer_mma< 80, 168, true , false>(smemc, su, A0_OFF, A1_OFF, 64, 208, 64, 208, 80,
                                      g_WB + G_B2, board_b2, wid, lane, tid);
    layer_mma< 64, 136, false, false>(smemc, su, A1_OFF, A0_OFF, 0, 144, 0, 144, 64,
                                      g_WB + G_H3, hand_b3,  wid, lane, tid);
    layer_mma< 80, 168, false, false>(smemc, su, A1_OFF, A0_OFF, 64, 208, 64, 208, 80,
                                      g_WB + G_B3, board_b3, wid, lane, tid);
    layer_mma<144, 296, true , false>(smemc, su, A0_OFF, A1_OFF, 0, 144, 0, 144, 144,
                                      g_WB + G_C1, hb_b1,    wid, lane, tid);
    layer_mma<144, 296, true , false>(smemc, su, A1_OFF, A0_OFF, 0, 144, 0, 144, 64,
                                      g_WB + G_C2, hb_b2,    wid, lane, tid);
    layer_mma< 64, 136, false, true >(smemc, su, A0_OFF, A1_OFF, 0, 144, 0, 0, 64,
                                      g_WB + G_C3, hb_b3,    wid, lane, tid);
    // final fp32 [128][64] staged at A1_OFF (trailing sync inside layer_mma)

    // ---- phase 3: assemble 312-float output rows --------------------------------
    const float* bufF = (const float*)(smemc + A1_OFF);
    const float* embTabs[6] = {pos_emb, action_emb, active_emb, street_emb, nump_emb, blind_emb};
    for (int g = tid; g < RTILE * 39; g += NTHREADS) {
        int row = g / 39, s = g % 39;
        float v[8];
        int kind = c_kind[s];
        if (kind == 0) {
            const float* f = bufF + row * 64 + s * 8;
            #pragma unroll
            for (int d = 0; d < 8; d++) v[d] = f[d];
        } else if (kind == 1) {
            int idx = (int)sst[row * 50 + c_p1[s]];
            const float* e = embTabs[c_p0[s]] + idx * 8;
            #pragma unroll
            for (int d = 0; d < 8; d++) v[d] = __ldg(e + d);
        } else {
            float x = sst[row * 50 + c_p0[s]];
            int wi = c_p1[s];
            #pragma unroll
            for (int d = 0; d < 8; d++)
                v[d] = fmaf(x, __ldg(scalar_W + wi * 8 + d), __ldg(scalar_b + wi * 8 + d));
        }
        float4* o = (float4*)(out + (size_t)(row0 + row) * 312 + s * 8);
        o[0] = make_float4(v[0], v[1], v[2], v[3]);
        o[1] = make_float4(v[4], v[5], v[6], v[7]);
    }
}

// ---------------- launch --------------------------------------------------------
extern "C" void kernel_launch(void* const* d_in, const int* in_sizes, int n_in,
                              void* d_out, int out_size)
{
    const float* state   = (const float*)d_in[0];
    const float* suit    = (const float*)d_in[1];
    const float* rank    = (const float*)d_in[2];
    const float* hW1 = (const float*)d_in[3];  const float* hb1 = (const float*)d_in[4];
    const float* hW2 = (const float*)d_in[5];  const float* hb2 = (const float*)d_in[6];
    const float* hW3 = (const float*)d_in[7];  const float* hb3 = (const float*)d_in[8];
    const float* bW1 = (const float*)d_in[9];  const float* bb1 = (const float*)d_in[10];
    const float* bW2 = (const float*)d_in[11]; const float* bb2 = (const float*)d_in[12];
    const float* bW3 = (const float*)d_in[13]; const float* bb3 = (const float*)d_in[14];
    const float* cW1 = (const float*)d_in[15]; const float* cb1 = (const float*)d_in[16];
    const float* cW2 = (const float*)d_in[17]; const float* cb2 = (const float*)d_in[18];
    const float* cW3 = (const float*)d_in[19]; const float* cb3 = (const float*)d_in[20];
    const float* pos    = (const float*)d_in[21];
    const float* action = (const float*)d_in[22];
    const float* activ  = (const float*)d_in[23];
    const float* street = (const float*)d_in[24];
    const float* nump   = (const float*)d_in[25];
    const float* blind  = (const float*)d_in[26];
    const float* sW     = (const float*)d_in[27];
    const float* sb     = (const float*)d_in[28];
    float* out = (float*)d_out;

    cudaFuncSetAttribute(preprocess_kernel,
                         cudaFuncAttributeMaxDynamicSharedMemorySize, SMEM_TOTAL);

    build_tables_kernel<<<49, 256>>>(suit, rank, hW1, bW1);
    pack_wb_kernel<<<(G_TOTAL + 255) / 256, 256>>>(hW2, hW3, bW2, bW3, cW1, cW2, cW3);

    const int nRows = 512 * 512;
    preprocess_kernel<<<nRows / RTILE, NTHREADS, SMEM_TOTAL>>>(
        state, hb1, bb1,
        hb2, hb3, bb2, bb3,
        cb1, cb2, cb3,
        pos, action, activ, street, nump, blind,
        sW, sb, out);
}

// round 15
// speedup vs baseline: 1.1577x; 1.1577x over previous
#include <cuda_runtime.h>
#include <cuda_bf16.h>

typedef unsigned int u32;
typedef unsigned long long u64;

#define NTHREADS 512
#define RTILE 128
#define SA 296              // A-buffer row stride (bf16 elems); 592B = conflict-free

// ---------------- smem map (bytes) ----------------------------------------------
#define A0_OFF   0          // A buffer 0: 128*296*2 = 75776
#define A1_OFF   75776      // A buffer 1: 75776
#define WB_OFF   151552     // weight ring: 2 x 37888
#define SLOTB    37888
#define SMEM_TOTAL 227328

// ---------------- weight image offsets (bf16 elems) ------------------------------
// image: [n rows][SB cols]: [0,K)=hi(W[k][n]), [K,2K)=lo, rest pad
#define G_H2 0       // 64 x 136
#define G_H3 8704
#define G_B2 17408   // 80 x 168
#define G_B3 30848
#define G_C1 44288   // 144 x 296
#define G_C2 86912   // 64 x 296
#define G_C3 105856  // 64 x 136
#define G_TOTAL 114560

__device__ float g_TH[4 * 19 * 64];
__device__ float g_TB[5 * 19 * 80];
__device__ __align__(16) __nv_bfloat16 g_WB[G_TOTAL];

// ---------------- output segment descriptors -------------------------------------
__device__ const int c_kind[39] = {0,0,0,0,0,0,0,0,
                                   1,1, 1,1,1,1,1, 1,1,1,1,1,
                                   2,2,2,2, 1,1,1, 2, 1,1,1, 1, 1,
                                   2,2,2,2,2,2};
__device__ const int c_p0[39]   = {0,0,0,0,0,0,0,0,
                                   3,0, 2,2,2,2,2, 0,0,0,0,0,
                                   40,41,42,43, 0,1,5, 39, 1,0,5, 4, 0,
                                   44,45,46,47,48,49};
__device__ const int c_p1[39]   = {0,0,0,0,0,0,0,0,
                                   18,20, 22,23,24,25,26, 27,28,29,30,31,
                                   0,2,3,5, 35,36,37, 1, 32,33,34, 19, 38,
                                   4,4,4,4,4,4};

__device__ __forceinline__ float leaky(float x) { return x > 0.f ? x : 0.01f * x; }

__device__ __forceinline__ u32 smem_u32(const void* p) {
    u32 a;
    asm("{ .reg .u64 t; cvta.to.shared.u64 t, %1; cvt.u32.u64 %0, t; }" : "=r"(a) : "l"(p));
    return a;
}
__device__ __forceinline__ void ldsm_x4(u32* r, u32 addr) {
    asm volatile("ldmatrix.sync.aligned.m8n8.x4.shared.b16 {%0,%1,%2,%3}, [%4];"
                 : "=r"(r[0]), "=r"(r[1]), "=r"(r[2]), "=r"(r[3]) : "r"(addr));
}
__device__ __forceinline__ void mma16816(float* d, const u32* a, const u32* b) {
    asm volatile("mma.sync.aligned.m16n8k16.row.col.f32.bf16.bf16.f32 "
                 "{%0,%1,%2,%3}, {%4,%5,%6,%7}, {%8,%9}, {%0,%1,%2,%3};"
                 : "+f"(d[0]), "+f"(d[1]), "+f"(d[2]), "+f"(d[3])
                 : "r"(a[0]), "r"(a[1]), "r"(a[2]), "r"(a[3]), "r"(b[0]), "r"(b[1]));
}
__device__ __forceinline__ void cp16(u32 dst, const void* src) {
    asm volatile("cp.async.cg.shared.global [%0], [%1], 16;" :: "r"(dst), "l"(src));
}
#define CP_COMMIT() asm volatile("cp.async.commit_group;" ::: "memory")
#define CP_WAIT0()  asm volatile("cp.async.wait_group 0;" ::: "memory")

__device__ __forceinline__ u32 bf16pack(float v0, float v1, float& l0, float& l1) {
    __nv_bfloat16 h0 = __float2bfloat16(v0), h1 = __float2bfloat16(v1);
    l0 = v0 - __bfloat162float(h0); l1 = v1 - __bfloat162float(h1);
    return (u32)__bfloat16_as_ushort(h0) | ((u32)__bfloat16_as_ushort(h1) << 16);
}
__device__ __forceinline__ u32 bf16pack2(float v0, float v1) {
    return (u32)__bfloat16_as_ushort(__float2bfloat16(v0)) |
           ((u32)__bfloat16_as_ushort(__float2bfloat16(v1)) << 16);
}

// ---------------- prologue 1: embedding->layer1 fp32 tables ----------------------
__global__ void build_tables_kernel(const float* __restrict__ suit_emb,
                                    const float* __restrict__ rank_emb,
                                    const float* __restrict__ hW1,
                                    const float* __restrict__ bW1)
{
    int i = blockIdx.x * blockDim.x + threadIdx.x;
    if (i < 4 * 19 * 64) {
        int j = i & 63, e = (i >> 6) % 19, c = i / (64 * 19);
        const float* emb; int dbase;
        if (e < 5) { emb = suit_emb + e * 8;        dbase = 16 * c; }
        else       { emb = rank_emb + (e - 5) * 8;  dbase = 16 * c + 8; }
        float s = 0.f;
        #pragma unroll
        for (int d = 0; d < 8; d++) s += emb[d] * hW1[(dbase + d) * 64 + j];
        g_TH[i] = s;
    } else {
        int ib = i - 4 * 19 * 64;
        if (ib < 5 * 19 * 80) {
            int j = ib % 80, e = (ib / 80) % 19, c = ib / (80 * 19);
            const float* emb; int dbase;
            if (e < 5) { emb = suit_emb + e * 8;       dbase = 16 * c; }
            else       { emb = rank_emb + (e - 5) * 8; dbase = 16 * c + 8; }
            float s = 0.f;
            #pragma unroll
            for (int d = 0; d < 8; d++) s += emb[d] * bW1[(dbase + d) * 80 + j];
            g_TB[ib] = s;
        }
    }
}

// ---------------- prologue 2: split weights into bf16 hi/lo images ---------------
__device__ __forceinline__ void pack_img(const float* __restrict__ W,
                                         int N, int K, int SB, int base, int e)
{
    int n = e / SB, c = e - n * SB;
    __nv_bfloat16 v;
    if (c < K) {
        v = __float2bfloat16(W[c * N + n]);
    } else if (c < 2 * K) {
        float w = W[(c - K) * N + n];
        __nv_bfloat16 h = __float2bfloat16(w);
        v = __float2bfloat16(w - __bfloat162float(h));
    } else {
        v = __float2bfloat16(0.f);
    }
    g_WB[base + e] = v;
}

__global__ void pack_wb_kernel(const float* __restrict__ hW2, const float* __restrict__ hW3,
                               const float* __restrict__ bW2, const float* __restrict__ bW3,
                               const float* __restrict__ cW1, const float* __restrict__ cW2,
                               const float* __restrict__ cW3)
{
    int i = blockIdx.x * blockDim.x + threadIdx.x;
    if      (i < G_H3)    pack_img(hW2, 64,  64,  136, G_H2, i - G_H2);
    else if (i < G_B2)    pack_img(hW3, 64,  64,  136, G_H3, i - G_H3);
    else if (i < G_B3)    pack_img(bW2, 80,  80,  168, G_B2, i - G_B2);
    else if (i < G_C1)    pack_img(bW3, 80,  80,  168, G_B3, i - G_B3);
    else if (i < G_C2)    pack_img(cW1, 144, 144, 296, G_C1, i - G_C1);
    else if (i < G_C3)    pack_img(cW2, 64,  144, 296, G_C2, i - G_C2);
    else if (i < G_TOTAL) pack_img(cW3, 64,  64,  136, G_C3, i - G_C3);
}

// ---------------- cp.async stage one weight chunk into a ring slot ---------------
__device__ __forceinline__ void issue_chunk(u32 dst, const char* src, int bytes, int tid)
{
    for (int i = tid * 16; i < bytes; i += NTHREADS * 16) cp16(dst + i, src + i);
    CP_COMMIT();
}

// ---------------- compute one 64- or 16-col chunk of a layer ---------------------
// A row-major [128][SA] bf16: hi cols [hiIn,hiIn+K), lo [loIn,loIn+K).
// Warp (rw=wid&7, wg=wid>>3): rows 16rw..16rw+15; tiles wg+2*ti (ti<NTILE).
// Shared fp32 accumulator per tile (3 split passes accumulate together).
template<int K, int SB, int CN, bool ACT, bool FINAL>
__device__ __forceinline__ void compute_chunk(char* smemc, u32 su, u32 wslot,
                                              int ainOff, int aoutOff,
                                              int hiIn, int loIn, int hiOut, int loOut,
                                              int n0, const float* __restrict__ bias,
                                              int wid, int lane)
{
    const int rw = wid & 7, wg = wid >> 3;
    const int m0 = rw * 16;
    const u32 aBase = su + (u32)ainOff + ((u32)(m0 + (lane & 15)) * SA + ((lane >> 4) << 3)) * 2;
    constexpr int NPAIR = (CN == 64) ? 2 : 1;       // ldsm pairs of 8-col tiles
    constexpr int NTILE = (CN == 64) ? 4 : 1;       // tiles per warp

    u32 bl[NPAIR];
    #pragma unroll
    for (int p = 0; p < NPAIR; p++) {
        int ta = wg + 4 * p;
        int tb = (CN == 64) ? ta + 2 : ta;          // CN==16: duplicate (unused half)
        int tsel = (lane < 16) ? ta : tb;
        bl[p] = wslot + ((u32)(tsel * 8 + (lane & 7)) * SB + (u32)(((lane >> 3) & 1) * 8)) * 2;
    }

    float acc[NTILE][4];
    #pragma unroll
    for (int t = 0; t < NTILE; t++)
        #pragma unroll
        for (int q = 0; q < 4; q++) acc[t][q] = 0.f;

    #pragma unroll
    for (int ks = 0; ks < K / 16; ks++) {
        const u32 ko = (u32)ks * 32;
        u32 ah[4], al[4];
        ldsm_x4(ah, aBase + (u32)hiIn * 2 + ko);
        ldsm_x4(al, aBase + (u32)loIn * 2 + ko);
        #pragma unroll
        for (int p = 0; p < NPAIR; p++) {
            u32 bh[4], blo[4];
            ldsm_x4(bh,  bl[p] + ko);
            ldsm_x4(blo, bl[p] + (u32)K * 2 + ko);
            mma16816(acc[2 * p], ah, &bh[0]);
            mma16816(acc[2 * p], ah, &blo[0]);
            mma16816(acc[2 * p], al, &bh[0]);
            if (NTILE > 1) {
                mma16816(acc[2 * p + 1], ah, &bh[2]);
                mma16816(acc[2 * p + 1], ah, &blo[2]);
                mma16816(acc[2 * p + 1], al, &bh[2]);
            }
        }
    }

    const int g2 = lane >> 2, tt = lane & 3;
    const int r0 = m0 + g2, r1 = r0 + 8;
    #pragma unroll
    for (int ti = 0; ti < NTILE; ti++) {
        const int col = n0 + (wg + 2 * ti) * 8 + 2 * tt;
        float b0 = __ldg(bias + col), b1 = __ldg(bias + col + 1);
        float v00 = acc[ti][0] + b0, v01 = acc[ti][1] + b1;
        float v10 = acc[ti][2] + b0, v11 = acc[ti][3] + b1;
        if (ACT) { v00 = leaky(v00); v01 = leaky(v01); v10 = leaky(v10); v11 = leaky(v11); }
        if (FINAL) {
            float* f = (float*)(smemc + aoutOff);
            *(float2*)(f + r0 * 64 + col) = make_float2(v00, v01);
            *(float2*)(f + r1 * 64 + col) = make_float2(v10, v11);
        } else {
            char* ab = smemc + aoutOff;
            float l00, l01, l10, l11;
            u32 h0 = bf16pack(v00, v01, l00, l01);
            u32 h1 = bf16pack(v10, v11, l10, l11);
            *(u32*)(ab + ((size_t)r0 * SA + hiOut + col) * 2) = h0;
            *(u32*)(ab + ((size_t)r1 * SA + hiOut + col) * 2) = h1;
            *(u32*)(ab + ((size_t)r0 * SA + loOut + col) * 2) = bf16pack2(l00, l01);
            *(u32*)(ab + ((size_t)r1 * SA + loOut + col) * 2) = bf16pack2(l10, l11);
        }
    }
}

// ---------------- fused main kernel ---------------------------------------------
__global__ void __launch_bounds__(NTHREADS, 1)
preprocess_kernel(const float* __restrict__ state,
                  const float* __restrict__ hand_b1, const float* __restrict__ board_b1,
                  const float* __restrict__ hand_b2, const float* __restrict__ hand_b3,
                  const float* __restrict__ board_b2, const float* __restrict__ board_b3,
                  const float* __restrict__ hb_b1, const float* __restrict__ hb_b2,
                  const float* __restrict__ hb_b3,
                  const float* __restrict__ pos_emb, const float* __restrict__ action_emb,
                  const float* __restrict__ active_emb, const float* __restrict__ street_emb,
                  const float* __restrict__ nump_emb, const float* __restrict__ blind_emb,
                  const float* __restrict__ scalar_W, const float* __restrict__ scalar_b,
                  float* __restrict__ out)
{
    extern __shared__ char smemc[];
    const u32 su = smem_u32(smemc);
    const int tid = threadIdx.x, lane = tid & 31, wid = tid >> 5;
    const int row0 = blockIdx.x * RTILE;
    const float* stb = state + (size_t)row0 * 50;
    const char* wb = (const char*)g_WB;
    const u32 s0 = su + WB_OFF, s1 = su + WB_OFF + SLOTB;

    // pre-stage first weight chunk; copy overlaps all of phase 1
    issue_chunk(s0, wb + 2 * G_H2, 64 * 136 * 2, tid);

    // ---- phase 1: exact fp32 table-sum layer-1, split-store into A0 -------------
    // hand: hi [0,64), lo [144,208); board: hi [64,144), lo [208,288)
    char* a0 = smemc + A0_OFF;
    for (int i = tid; i < RTILE * 32; i += NTHREADS) {
        int row = i >> 5, cp = (i & 31) * 2;
        const float* st = stb + row * 50;           // warp-uniform row -> broadcast LDG
        float s0f = __ldg(hand_b1 + cp), s1f = __ldg(hand_b1 + cp + 1);
        #pragma unroll
        for (int c = 0; c < 4; c++) {
            int r = (int)__ldg(st + 2 * c), sv = (int)__ldg(st + 2 * c + 1);
            float2 t1 = *(const float2*)&g_TH[(c * 19 + sv) * 64 + cp];
            float2 t2 = *(const float2*)&g_TH[(c * 19 + 5 + r) * 64 + cp];
            s0f += t1.x + t2.x; s1f += t1.y + t2.y;
        }
        s0f = leaky(s0f); s1f = leaky(s1f);
        float l0, l1;
        *(u32*)(a0 + ((size_t)row * SA + cp) * 2)       = bf16pack(s0f, s1f, l0, l1);
        *(u32*)(a0 + ((size_t)row * SA + 144 + cp) * 2) = bf16pack2(l0, l1);
    }
    for (int i = tid; i < RTILE * 40; i += NTHREADS) {
        int row = i / 40, cp = (i % 40) * 2;
        const float* st = stb + row * 50;
        float s0f = __ldg(board_b1 + cp), s1f = __ldg(board_b1 + cp + 1);
        #pragma unroll
        for (int c = 0; c < 5; c++) {
            int r = (int)__ldg(st + 8 + 2 * c), sv = (int)__ldg(st + 9 + 2 * c);
            float2 t1 = *(const float2*)&g_TB[(c * 19 + sv) * 80 + cp];
            float2 t2 = *(const float2*)&g_TB[(c * 19 + 5 + r) * 80 + cp];
            s0f += t1.x + t2.x; s1f += t1.y + t2.y;
        }
        s0f = leaky(s0f); s1f = leaky(s1f);
        float l0, l1;
        *(u32*)(a0 + ((size_t)row * SA + 64 + cp) * 2)  = bf16pack(s0f, s1f, l0, l1);
        *(u32*)(a0 + ((size_t)row * SA + 208 + cp) * 2) = bf16pack2(l0, l1);
    }

    // ---- flat chunk pipeline: wait -> sync -> issue(next) -> compute(cur) -------
    // chunk sequence (slot alternates s0,s1,...):
    //  0 H2(0,64)  1 B2(0,64)  2 B2(64,16)  3 H3(0,64)  4 B3(0,64)  5 B3(64,16)
    //  6 C1(0,64)  7 C1(64,64) 8 C1(128,16) 9 C2(0,64) 10 C3(0,64,FINAL)
    #define STEP(SLOT, ISSUE, CALL) \
        CP_WAIT0(); __syncthreads(); ISSUE; CALL;

    STEP(s0, issue_chunk(s1, wb + 2 * G_B2, 64 * 168 * 2, tid),
         (compute_chunk<64, 136, 64, true, false>(smemc, su, s0, A0_OFF, A1_OFF, 0, 144, 0, 144, 0, hand_b2, wid, lane)));
    STEP(s1, issue_chunk(s0, wb + 2 * (G_B2 + 64 * 168), 16 * 168 * 2, tid),
         (compute_chunk<80, 168, 64, true, false>(smemc, su, s1, A0_OFF, A1_OFF, 64, 208, 64, 208, 0, board_b2, wid, lane)));
    STEP(s0, issue_chunk(s1, wb + 2 * G_H3, 64 * 136 * 2, tid),
         (compute_chunk<80, 168, 16, true, false>(smemc, su, s0, A0_OFF, A1_OFF, 64, 208, 64, 208, 64, board_b2, wid, lane)));
    STEP(s1, issue_chunk(s0, wb + 2 * G_B3, 64 * 168 * 2, tid),
         (compute_chunk<64, 136, 64, false, false>(smemc, su, s1, A1_OFF, A0_OFF, 0, 144, 0, 144, 0, hand_b3, wid, lane)));
    STEP(s0, issue_chunk(s1, wb + 2 * (G_B3 + 64 * 168), 16 * 168 * 2, tid),
         (compute_chunk<80, 168, 64, false, false>(smemc, su, s0, A1_OFF, A0_OFF, 64, 208, 64, 208, 0, board_b3, wid, lane)));
    STEP(s1, issue_chunk(s0, wb + 2 * G_C1, 64 * 296 * 2, tid),
         (compute_chunk<80, 168, 16, false, false>(smemc, su, s1, A1_OFF, A0_OFF, 64, 208, 64, 208, 64, board_b3, wid, lane)));
    STEP(s0, issue_chunk(s1, wb + 2 * (G_C1 + 64 * 296), 64 * 296 * 2, tid),
         (compute_chunk<144, 296, 64, true, false>(smemc, su, s0, A0_OFF, A1_OFF, 0, 144, 0, 144, 0, hb_b1, wid, lane)));
    STEP(s1, issue_chunk(s0, wb + 2 * (G_C1 + 128 * 296), 16 * 296 * 2, tid),
         (compute_chunk<144, 296, 64, true, false>(smemc, su, s1, A0_OFF, A1_OFF, 0, 144, 0, 144, 64, hb_b1, wid, lane)));
    STEP(s0, issue_chunk(s1, wb + 2 * G_C2, 64 * 296 * 2, tid),
         (compute_chunk<144, 296, 16, true, false>(smemc, su, s0, A0_OFF, A1_OFF, 0, 144, 0, 144, 128, hb_b1, wid, lane)));
    STEP(s1, issue_chunk(s0, wb + 2 * G_C3, 64 * 136 * 2, tid),
         (compute_chunk<144, 296, 64, true, false>(smemc, su, s1, A1_OFF, A0_OFF, 0, 144, 0, 144, 0, hb_b2, wid, lane)));
    STEP(s0, ,
         (compute_chunk<64, 136, 64, false, true>(smemc, su, s0, A0_OFF, A1_OFF, 0, 144, 0, 0, 0, hb_b3, wid, lane)));
    #undef STEP
    __syncthreads();
    // final fp32 [128][64] staged at A1_OFF

    // ---- phase 3: assemble 312-float output rows --------------------------------
    const float* bufF = (const float*)(smemc + A1_OFF);
    const float* embTabs[6] = {pos_emb, action_emb, active_emb, street_emb, nump_emb, blind_emb};
    for (int g = tid; g < RTILE * 39; g += NTHREADS) {
        int row = g / 39, s = g % 39;
        float v[8];
        int kind = c_kind[s];
        if (kind == 0) {
            const float* f = bufF + row * 64 + s * 8;
            #pragma unroll
            for (int d = 0; d < 8; d++) v[d] = f[d];
        } else if (kind == 1) {
            int idx = (int)__ldg(stb + row * 50 + c_p1[s]);
            const float* e = embTabs[c_p0[s]] + idx * 8;
            #pragma unroll
            for (int d = 0; d < 8; d++) v[d] = __ldg(e + d);
        } else {
            float x = __ldg(stb + row * 50 + c_p0[s]);
            int wi = c_p1[s];
            #pragma unroll
            for (int d = 0; d < 8; d++)
                v[d] = fmaf(x, __ldg(scalar_W + wi * 8 + d), __ldg(scalar_b + wi * 8 + d));
        }
        float4* o = (float4*)(out + (size_t)(row0 + row) * 312 + s * 8);
        o[0] = make_float4(v[0], v[1], v[2], v[3]);
        o[1] = make_float4(v[4], v[5], v[6], v[7]);
    }
}

// ---------------- launch --------------------------------------------------------
extern "C" void kernel_launch(void* const* d_in, const int* in_sizes, int n_in,
                              void* d_out, int out_size)
{
    const float* state   = (const float*)d_in[0];
    const float* suit    = (const float*)d_in[1];
    const float* rank    = (const float*)d_in[2];
    const float* hW1 = (const float*)d_in[3];  const float* hb1 = (const float*)d_in[4];
    const float* hW2 = (const float*)d_in[5];  const float* hb2 = (const float*)d_in[6];
    const float* hW3 = (const float*)d_in[7];  const float* hb3 = (const float*)d_in[8];
    const float* bW1 = (const float*)d_in[9];  const float* bb1 = (const float*)d_in[10];
    const float* bW2 = (const float*)d_in[11]; const float* bb2 = (const float*)d_in[12];
    const float* bW3 = (const float*)d_in[13]; const float* bb3 = (const float*)d_in[14];
    const float* cW1 = (const float*)d_in[15]; const float* cb1 = (const float*)d_in[16];
    const float* cW2 = (const float*)d_in[17]; const float* cb2 = (const float*)d_in[18];
    const float* cW3 = (const float*)d_in[19]; const float* cb3 = (const float*)d_in[20];
    const float* pos    = (const float*)d_in[21];
    const float* action = (const float*)d_in[22];
    const float* activ  = (const float*)d_in[23];
    const float* street = (const float*)d_in[24];
    const float* nump   = (const float*)d_in[25];
    const float* blind  = (const float*)d_in[26];
    const float* sW     = (const float*)d_in[27];
    const float* sb     = (const float*)d_in[28];
    float* out = (float*)d_out;

    cudaFuncSetAttribute(preprocess_kernel,
                         cudaFuncAttributeMaxDynamicSharedMemorySize, SMEM_TOTAL);

    build_tables_kernel<<<49, 256>>>(suit, rank, hW1, bW1);
    pack_wb_kernel<<<(G_TOTAL + 255) / 256, 256>>>(hW2, hW3, bW2, bW3, cW1, cW2, cW3);

    const int nRows = 512 * 512;
    preprocess_kernel<<<nRows / RTILE, NTHREADS, SMEM_TOTAL>>>(
        state, hb1, bb1,
        hb2, hb3, bb2, bb3,
        cb1, cb2, cb3,
        pos, action, activ, street, nump, blind,
        sW, sb, out);
}

// round 16
// speedup vs baseline: 1.3764x; 1.1889x over previous
#include <cuda_runtime.h>
#include <cuda_fp16.h>

typedef unsigned int u32;
typedef unsigned long long u64;

#define NTHREADS 512
#define RTILE 128
#define SA 296              // A-buffer row stride (fp16 elems); 592B = conflict-free

// ---------------- smem map (bytes) ----------------------------------------------
#define A0_OFF   0          // A buffer 0: 128*296*2 = 75776
#define A1_OFF   75776      // A buffer 1: 75776
#define WB_OFF   151552     // weight ring: 2 x 37888
#define SLOTB    37888
#define SMEM_TOTAL 227328

// ---------------- weight image offsets (fp16 elems) ------------------------------
// image: [n rows][SB cols]: [0,K)=hi(W[k][n]), [K,2K)=lo, rest pad
#define G_H2 0       // 64 x 136
#define G_H3 8704
#define G_B2 17408   // 80 x 168
#define G_B3 30848
#define G_C1 44288   // 144 x 296
#define G_C2 86912   // 64 x 296
#define G_C3 105856  // 64 x 136
#define G_TOTAL 114560

__device__ float g_TH[4 * 19 * 64];
__device__ float g_TB[5 * 19 * 80];
__device__ __align__(16) __half g_WB[G_TOTAL];

// ---------------- output segment descriptors -------------------------------------
__device__ const int c_kind[39] = {0,0,0,0,0,0,0,0,
                                   1,1, 1,1,1,1,1, 1,1,1,1,1,
                                   2,2,2,2, 1,1,1, 2, 1,1,1, 1, 1,
                                   2,2,2,2,2,2};
__device__ const int c_p0[39]   = {0,0,0,0,0,0,0,0,
                                   3,0, 2,2,2,2,2, 0,0,0,0,0,
                                   40,41,42,43, 0,1,5, 39, 1,0,5, 4, 0,
                                   44,45,46,47,48,49};
__device__ const int c_p1[39]   = {0,0,0,0,0,0,0,0,
                                   18,20, 22,23,24,25,26, 27,28,29,30,31,
                                   0,2,3,5, 35,36,37, 1, 32,33,34, 19, 38,
                                   4,4,4,4,4,4};

__device__ __forceinline__ float leaky(float x) { return x > 0.f ? x : 0.01f * x; }

__device__ __forceinline__ u32 smem_u32(const void* p) {
    u32 a;
    asm("{ .reg .u64 t; cvta.to.shared.u64 t, %1; cvt.u32.u64 %0, t; }" : "=r"(a) : "l"(p));
    return a;
}
__device__ __forceinline__ void ldsm_x4(u32* r, u32 addr) {
    asm volatile("ldmatrix.sync.aligned.m8n8.x4.shared.b16 {%0,%1,%2,%3}, [%4];"
                 : "=r"(r[0]), "=r"(r[1]), "=r"(r[2]), "=r"(r[3]) : "r"(addr));
}
__device__ __forceinline__ void mma16816(float* d, const u32* a, const u32* b) {
    asm volatile("mma.sync.aligned.m16n8k16.row.col.f32.f16.f16.f32 "
                 "{%0,%1,%2,%3}, {%4,%5,%6,%7}, {%8,%9}, {%0,%1,%2,%3};"
                 : "+f"(d[0]), "+f"(d[1]), "+f"(d[2]), "+f"(d[3])
                 : "r"(a[0]), "r"(a[1]), "r"(a[2]), "r"(a[3]), "r"(b[0]), "r"(b[1]));
}
__device__ __forceinline__ void cp16(u32 dst, const void* src) {
    asm volatile("cp.async.cg.shared.global [%0], [%1], 16;" :: "r"(dst), "l"(src));
}
#define CP_COMMIT() asm volatile("cp.async.commit_group;" ::: "memory")
#define CP_WAIT0()  asm volatile("cp.async.wait_group 0;" ::: "memory")

// pack two fp32 into fp16x2 (round-to-nearest)
__device__ __forceinline__ u32 f16pack2(float a, float b) {
    __half2 h = __floats2half2_rn(a, b);
    return *(u32*)&h;
}

// ---------------- prologue 1: embedding->layer1 fp32 tables ----------------------
__global__ void build_tables_kernel(const float* __restrict__ suit_emb,
                                    const float* __restrict__ rank_emb,
                                    const float* __restrict__ hW1,
                                    const float* __restrict__ bW1)
{
    int i = blockIdx.x * blockDim.x + threadIdx.x;
    if (i < 4 * 19 * 64) {
        int j = i & 63, e = (i >> 6) % 19, c = i / (64 * 19);
        const float* emb; int dbase;
        if (e < 5) { emb = suit_emb + e * 8;        dbase = 16 * c; }
        else       { emb = rank_emb + (e - 5) * 8;  dbase = 16 * c + 8; }
        float s = 0.f;
        #pragma unroll
        for (int d = 0; d < 8; d++) s += emb[d] * hW1[(dbase + d) * 64 + j];
        g_TH[i] = s;
    } else {
        int ib = i - 4 * 19 * 64;
        if (ib < 5 * 19 * 80) {
            int j = ib % 80, e = (ib / 80) % 19, c = ib / (80 * 19);
            const float* emb; int dbase;
            if (e < 5) { emb = suit_emb + e * 8;       dbase = 16 * c; }
            else       { emb = rank_emb + (e - 5) * 8; dbase = 16 * c + 8; }
            float s = 0.f;
            #pragma unroll
            for (int d = 0; d < 8; d++) s += emb[d] * bW1[(dbase + d) * 80 + j];
            g_TB[ib] = s;
        }
    }
}

// ---------------- prologue 2: split weights into fp16 hi/lo images ---------------
__device__ __forceinline__ void pack_img(const float* __restrict__ W,
                                         int N, int K, int SB, int base, int e)
{
    int n = e / SB, c = e - n * SB;
    __half v;
    if (c < K) {
        v = __float2half_rn(W[c * N + n]);
    } else if (c < 2 * K) {
        float w = W[(c - K) * N + n];
        __half h = __float2half_rn(w);
        v = __float2half_rn(w - __half2float(h));
    } else {
        v = __float2half_rn(0.f);
    }
    g_WB[base + e] = v;
}

__global__ void pack_wb_kernel(const float* __restrict__ hW2, const float* __restrict__ hW3,
                               const float* __restrict__ bW2, const float* __restrict__ bW3,
                               const float* __restrict__ cW1, const float* __restrict__ cW2,
                               const float* __restrict__ cW3)
{
    int i = blockIdx.x * blockDim.x + threadIdx.x;
    if      (i < G_H3)    pack_img(hW2, 64,  64,  136, G_H2, i - G_H2);
    else if (i < G_B2)    pack_img(hW3, 64,  64,  136, G_H3, i - G_H3);
    else if (i < G_B3)    pack_img(bW2, 80,  80,  168, G_B2, i - G_B2);
    else if (i < G_C1)    pack_img(bW3, 80,  80,  168, G_B3, i - G_B3);
    else if (i < G_C2)    pack_img(cW1, 144, 144, 296, G_C1, i - G_C1);
    else if (i < G_C3)    pack_img(cW2, 64,  144, 296, G_C2, i - G_C2);
    else if (i < G_TOTAL) pack_img(cW3, 64,  64,  136, G_C3, i - G_C3);
}

// ---------------- cp.async stage one weight chunk into a ring slot ---------------
__device__ __forceinline__ void issue_chunk(u32 dst, const char* src, int bytes, int tid)
{
    for (int i = tid * 16; i < bytes; i += NTHREADS * 16) cp16(dst + i, src + i);
    CP_COMMIT();
}

// ---------------- compute one 64- or 16-col chunk of a layer ---------------------
// A row-major [128][SA] fp16 (hi only): cols [hiIn, hiIn+K).
// B image per chunk: [cn rows][SB]: hi at [0,K), lo at [K,2K).
// 2-pass: acc += A_hi*B_hi + A_hi*B_lo. Warp (rw=wid&7, wg=wid>>3):
// rows 16rw..16rw+15; tiles wg+2*ti (ti<NTILE).
template<int K, int SB, int CN, bool ACT, bool FINAL>
__device__ __forceinline__ void compute_chunk(char* smemc, u32 su, u32 wslot,
                                              int ainOff, int aoutOff,
                                              int hiIn, int hiOut,
                                              int n0, const float* __restrict__ bias,
                                              int wid, int lane)
{
    const int rw = wid & 7, wg = wid >> 3;
    const int m0 = rw * 16;
    const u32 aBase = su + (u32)ainOff + ((u32)(m0 + (lane & 15)) * SA + ((lane >> 4) << 3)) * 2;
    constexpr int NPAIR = (CN == 64) ? 2 : 1;       // ldsm pairs of 8-col tiles
    constexpr int NTILE = (CN == 64) ? 4 : 1;       // tiles per warp

    u32 bl[NPAIR];
    #pragma unroll
    for (int p = 0; p < NPAIR; p++) {
        int ta = wg + 4 * p;
        int tb = (CN == 64) ? ta + 2 : ta;          // CN==16: duplicate (unused half)
        int tsel = (lane < 16) ? ta : tb;
        bl[p] = wslot + ((u32)(tsel * 8 + (lane & 7)) * SB + (u32)(((lane >> 3) & 1) * 8)) * 2;
    }

    float acc[NTILE][4];
    #pragma unroll
    for (int t = 0; t < NTILE; t++)
        #pragma unroll
        for (int q = 0; q < 4; q++) acc[t][q] = 0.f;

    #pragma unroll
    for (int ks = 0; ks < K / 16; ks++) {
        const u32 ko = (u32)ks * 32;
        u32 ah[4];
        ldsm_x4(ah, aBase + (u32)hiIn * 2 + ko);
        #pragma unroll
        for (int p = 0; p < NPAIR; p++) {
            u32 bh[4], blo[4];
            ldsm_x4(bh,  bl[p] + ko);
            ldsm_x4(blo, bl[p] + (u32)K * 2 + ko);
            mma16816(acc[2 * p], ah, &bh[0]);
            mma16816(acc[2 * p], ah, &blo[0]);
            if (NTILE > 1) {
                mma16816(acc[2 * p + 1], ah, &bh[2]);
                mma16816(acc[2 * p + 1], ah, &blo[2]);
            }
        }
    }

    const int g2 = lane >> 2, tt = lane & 3;
    const int r0 = m0 + g2, r1 = r0 + 8;
    #pragma unroll
    for (int ti = 0; ti < NTILE; ti++) {
        const int col = n0 + (wg + 2 * ti) * 8 + 2 * tt;
        float b0 = __ldg(bias + col), b1 = __ldg(bias + col + 1);
        float v00 = acc[ti][0] + b0, v01 = acc[ti][1] + b1;
        float v10 = acc[ti][2] + b0, v11 = acc[ti][3] + b1;
        if (ACT) { v00 = leaky(v00); v01 = leaky(v01); v10 = leaky(v10); v11 = leaky(v11); }
        if (FINAL) {
            float* f = (float*)(smemc + aoutOff);
            *(float2*)(f + r0 * 64 + col) = make_float2(v00, v01);
            *(float2*)(f + r1 * 64 + col) = make_float2(v10, v11);
        } else {
            char* ab = smemc + aoutOff;
            *(u32*)(ab + ((size_t)r0 * SA + hiOut + col) * 2) = f16pack2(v00, v01);
            *(u32*)(ab + ((size_t)r1 * SA + hiOut + col) * 2) = f16pack2(v10, v11);
        }
    }
}

// ---------------- fused main kernel ---------------------------------------------
__global__ void __launch_bounds__(NTHREADS, 1)
preprocess_kernel(const float* __restrict__ state,
                  const float* __restrict__ hand_b1, const float* __restrict__ board_b1,
                  const float* __restrict__ hand_b2, const float* __restrict__ hand_b3,
                  const float* __restrict__ board_b2, const float* __restrict__ board_b3,
                  const float* __restrict__ hb_b1, const float* __restrict__ hb_b2,
                  const float* __restrict__ hb_b3,
                  const float* __restrict__ pos_emb, const float* __restrict__ action_emb,
                  const float* __restrict__ active_emb, const float* __restrict__ street_emb,
                  const float* __restrict__ nump_emb, const float* __restrict__ blind_emb,
                  const float* __restrict__ scalar_W, const float* __restrict__ scalar_b,
                  float* __restrict__ out)
{
    extern __shared__ char smemc[];
    const u32 su = smem_u32(smemc);
    const int tid = threadIdx.x, lane = tid & 31, wid = tid >> 5;
    const int row0 = blockIdx.x * RTILE;
    const float* stb = state + (size_t)row0 * 50;
    const char* wb = (const char*)g_WB;
    const u32 s0 = su + WB_OFF, s1 = su + WB_OFF + SLOTB;

    // pre-stage first weight chunk; copy overlaps all of phase 1
    issue_chunk(s0, wb + 2 * G_H2, 64 * 136 * 2, tid);

    // ---- phase 1: exact fp32 table-sum layer-1, fp16-hi store into A0 -----------
    // hand: hi [0,64); board: hi [64,144)
    char* a0 = smemc + A0_OFF;
    for (int i = tid; i < RTILE * 32; i += NTHREADS) {
        int row = i >> 5, cp = (i & 31) * 2;
        const float* st = stb + row * 50;           // warp-uniform row -> broadcast LDG
        float s0f = __ldg(hand_b1 + cp), s1f = __ldg(hand_b1 + cp + 1);
        #pragma unroll
        for (int c = 0; c < 4; c++) {
            int r = (int)__ldg(st + 2 * c), sv = (int)__ldg(st + 2 * c + 1);
            float2 t1 = *(const float2*)&g_TH[(c * 19 + sv) * 64 + cp];
            float2 t2 = *(const float2*)&g_TH[(c * 19 + 5 + r) * 64 + cp];
            s0f += t1.x + t2.x; s1f += t1.y + t2.y;
        }
        *(u32*)(a0 + ((size_t)row * SA + cp) * 2) = f16pack2(leaky(s0f), leaky(s1f));
    }
    for (int i = tid; i < RTILE * 40; i += NTHREADS) {
        int row = i / 40, cp = (i % 40) * 2;
        const float* st = stb + row * 50;
        float s0f = __ldg(board_b1 + cp), s1f = __ldg(board_b1 + cp + 1);
        #pragma unroll
        for (int c = 0; c < 5; c++) {
            int r = (int)__ldg(st + 8 + 2 * c), sv = (int)__ldg(st + 9 + 2 * c);
            float2 t1 = *(const float2*)&g_TB[(c * 19 + sv) * 80 + cp];
            float2 t2 = *(const float2*)&g_TB[(c * 19 + 5 + r) * 80 + cp];
            s0f += t1.x + t2.x; s1f += t1.y + t2.y;
        }
        *(u32*)(a0 + ((size_t)row * SA + 64 + cp) * 2) = f16pack2(leaky(s0f), leaky(s1f));
    }

    // ---- flat chunk pipeline: wait -> sync -> issue(next) -> compute(cur) -------
    // chunk sequence (slot alternates s0,s1,...):
    //  0 H2(0,64)  1 B2(0,64)  2 B2(64,16)  3 H3(0,64)  4 B3(0,64)  5 B3(64,16)
    //  6 C1(0,64)  7 C1(64,64) 8 C1(128,16) 9 C2(0,64) 10 C3(0,64,FINAL)
    #define STEP(ISSUE, CALL) \
        CP_WAIT0(); __syncthreads(); ISSUE; CALL;

    STEP(issue_chunk(s1, wb + 2 * G_B2, 64 * 168 * 2, tid),
         (compute_chunk<64, 136, 64, true, false>(smemc, su, s0, A0_OFF, A1_OFF, 0, 0, 0, hand_b2, wid, lane)));
    STEP(issue_chunk(s0, wb + 2 * (G_B2 + 64 * 168), 16 * 168 * 2, tid),
         (compute_chunk<80, 168, 64, true, false>(smemc, su, s1, A0_OFF, A1_OFF, 64, 64, 0, board_b2, wid, lane)));
    STEP(issue_chunk(s1, wb + 2 * G_H3, 64 * 136 * 2, tid),
         (compute_chunk<80, 168, 16, true, false>(smemc, su, s0, A0_OFF, A1_OFF, 64, 64, 64, board_b2, wid, lane)));
    STEP(issue_chunk(s0, wb + 2 * G_B3, 64 * 168 * 2, tid),
         (compute_chunk<64, 136, 64, false, false>(smemc, su, s1, A1_OFF, A0_OFF, 0, 0, 0, hand_b3, wid, lane)));
    STEP(issue_chunk(s1, wb + 2 * (G_B3 + 64 * 168), 16 * 168 * 2, tid),
         (compute_chunk<80, 168, 64, false, false>(smemc, su, s0, A1_OFF, A0_OFF, 64, 64, 0, board_b3, wid, lane)));
    STEP(issue_chunk(s0, wb + 2 * G_C1, 64 * 296 * 2, tid),
         (compute_chunk<80, 168, 16, false, false>(smemc, su, s1, A1_OFF, A0_OFF, 64, 64, 64, board_b3, wid, lane)));
    STEP(issue_chunk(s1, wb + 2 * (G_C1 + 64 * 296), 64 * 296 * 2, tid),
         (compute_chunk<144, 296, 64, true, false>(smemc, su, s0, A0_OFF, A1_OFF, 0, 0, 0, hb_b1, wid, lane)));
    STEP(issue_chunk(s0, wb + 2 * (G_C1 + 128 * 296), 16 * 296 * 2, tid),
         (compute_chunk<144, 296, 64, true, false>(smemc, su, s1, A0_OFF, A1_OFF, 0, 0, 64, hb_b1, wid, lane)));
    STEP(issue_chunk(s1, wb + 2 * G_C2, 64 * 296 * 2, tid),
         (compute_chunk<144, 296, 16, true, false>(smemc, su, s0, A0_OFF, A1_OFF, 0, 0, 128, hb_b1, wid, lane)));
    STEP(issue_chunk(s0, wb + 2 * G_C3, 64 * 136 * 2, tid),
         (compute_chunk<144, 296, 64, true, false>(smemc, su, s1, A1_OFF, A0_OFF, 0, 0, 0, hb_b2, wid, lane)));
    STEP(,
         (compute_chunk<64, 136, 64, false, true>(smemc, su, s0, A0_OFF, A1_OFF, 0, 0, 0, hb_b3, wid, lane)));
    #undef STEP
    __syncthreads();
    // final fp32 [128][64] staged at A1_OFF

    // ---- phase 3: assemble 312-float output rows --------------------------------
    const float* bufF = (const float*)(smemc + A1_OFF);
    const float* embTabs[6] = {pos_emb, action_emb, active_emb, street_emb, nump_emb, blind_emb};
    for (int g = tid; g < RTILE * 39; g += NTHREADS) {
        int row = g / 39, s = g % 39;
        float v[8];
        int kind = c_kind[s];
        if (kind == 0) {
            const float* f = bufF + row * 64 + s * 8;
            #pragma unroll
            for (int d = 0; d < 8; d++) v[d] = f[d];
        } else if (kind == 1) {
            int idx = (int)__ldg(stb + row * 50 + c_p1[s]);
            const float* e = embTabs[c_p0[s]] + idx * 8;
            #pragma unroll
            for (int d = 0; d < 8; d++) v[d] = __ldg(e + d);
        } else {
            float x = __ldg(stb + row * 50 + c_p0[s]);
            int wi = c_p1[s];
            #pragma unroll
            for (int d = 0; d < 8; d++)
                v[d] = fmaf(x, __ldg(scalar_W + wi * 8 + d), __ldg(scalar_b + wi * 8 + d));
        }
        float4* o = (float4*)(out + (size_t)(row0 + row) * 312 + s * 8);
        o[0] = make_float4(v[0], v[1], v[2], v[3]);
        o[1] = make_float4(v[4], v[5], v[6], v[7]);
    }
}

// ---------------- launch --------------------------------------------------------
extern "C" void kernel_launch(void* const* d_in, const int* in_sizes, int n_in,
                              void* d_out, int out_size)
{
    const float* state   = (const float*)d_in[0];
    const float* suit    = (const float*)d_in[1];
    const float* rank    = (const float*)d_in[2];
    const float* hW1 = (const float*)d_in[3];  const float* hb1 = (const float*)d_in[4];
    const float* hW2 = (const float*)d_in[5];  const float* hb2 = (const float*)d_in[6];
    const float* hW3 = (const float*)d_in[7];  const float* hb3 = (const float*)d_in[8];
    const float* bW1 = (const float*)d_in[9];  const float* bb1 = (const float*)d_in[10];
    const float* bW2 = (const float*)d_in[11]; const float* bb2 = (const float*)d_in[12];
    const float* bW3 = (const float*)d_in[13]; const float* bb3 = (const float*)d_in[14];
    const float* cW1 = (const float*)d_in[15]; const float* cb1 = (const float*)d_in[16];
    const float* cW2 = (const float*)d_in[17]; const float* cb2 = (const float*)d_in[18];
    const float* cW3 = (const float*)d_in[19]; const float* cb3 = (const float*)d_in[20];
    const float* pos    = (const float*)d_in[21];
    const float* action = (const float*)d_in[22];
    const float* activ  = (const float*)d_in[23];
    const float* street = (const float*)d_in[24];
    const float* nump   = (const float*)d_in[25];
    const float* blind  = (const float*)d_in[26];
    const float* sW     = (const float*)d_in[27];
    const float* sb     = (const float*)d_in[28];
    float* out = (float*)d_out;

    cudaFuncSetAttribute(preprocess_kernel,
                         cudaFuncAttributeMaxDynamicSharedMemorySize, SMEM_TOTAL);

    build_tables_kernel<<<49, 256>>>(suit, rank, hW1, bW1);
    pack_wb_kernel<<<(G_TOTAL + 255) / 256, 256>>>(hW2, hW3, bW2, bW3, cW1, cW2, cW3);

    const int nRows = 512 * 512;
    preprocess_kernel<<<nRows / RTILE, NTHREADS, SMEM_TOTAL>>>(
        state, hb1, bb1,
        hb2, hb3, bb2, bb3,
        cb1, cb2, cb3,
        pos, action, activ, street, nump, blind,
        sW, sb, out);
}